// round 2
// baseline (speedup 1.0000x reference)
#include <cuda_runtime.h>
#include <math.h>

#define NN 8
#define HH 12
#define DHD 64
#define LV 1568
#define LA 512
#define NCV 392
#define NCA 256
#define NHNH (NN*HH)          // 96
#define OSTR 5696             // output row stride
#define RS_V 8                // row-splits for v_pos accumulation (256/8 = 32 rows per block)
#define RS_A 8                // row-splits for a_pos accumulation (392/8 = 49 rows per block)
#define SCALEF 0.125f

// ---- scratch (device globals; no allocation allowed) ----
__device__ float g_w_av[NN * NCV];
__device__ float g_w_va[NN * NCA];
__device__ float g_sum_av[NN];
__device__ float g_sum_va[NN];
__device__ float g_vpos[RS_V * NHNH * LV];   // partial accumulators, full LV columns
__device__ float g_apos[RS_A * NHNH * LA];   // partial accumulators, full LA columns

// K0: gather weights, compute their sums, fill output defaults (prob=0, prune=n_attn)
__global__ void k0_prep(const float* __restrict__ n_attn_av,
                        const float* __restrict__ n_attn_va,
                        const int* __restrict__ ids_v,
                        const int* __restrict__ ids_a,
                        float* __restrict__ out) {
    int n = blockIdx.x;
    int t = threadIdx.x;             // 512 threads
    __shared__ float red[512];

    float wv = 0.f;
    if (t < NCV) {
        int p = ids_v[n * LV + t];
        wv = n_attn_av[n * LV + p];
        g_w_av[n * NCV + t] = wv;
    }
    red[t] = wv;
    __syncthreads();
    for (int s = 256; s > 0; s >>= 1) {
        if (t < s) red[t] += red[t + s];
        __syncthreads();
    }
    if (t == 0) g_sum_av[n] = red[0];
    __syncthreads();

    float wa = 0.f;
    if (t < NCA) {
        int p = ids_a[n * LA + t];
        wa = n_attn_va[n * LA + p];
        g_w_va[n * NCA + t] = wa;
    }
    red[t] = wa;
    __syncthreads();
    for (int s = 256; s > 0; s >>= 1) {
        if (t < s) red[t] += red[t + s];
        __syncthreads();
    }
    if (t == 0) g_sum_va[n] = red[0];

    // output defaults
    float* o = out + n * OSTR;
    for (int i = t; i < LV + LA; i += 512) o[i] = 0.f;                       // prob regions
    for (int i = t; i < LV; i += 512) o[3616 + i] = n_attn_av[n * LV + i];   // prune_av default
    for (int i = t; i < LA; i += 512) o[5184 + i] = n_attn_va[n * LA + i];   // prune_va default
}

// K1: v_pos partial accumulators: acc[c] += w_va[a] * cross_av[n,h,idx_a[a],c] over a row-split
__global__ void k1_vpos(const float* __restrict__ cross_av,
                        const int* __restrict__ ids_a) {
    const int nh = blockIdx.z;
    const int n = nh / HH;
    const int y = blockIdx.y;                       // row split
    const int g = blockIdx.x * 256 + threadIdx.x;   // float4 column group (LV/4 = 392 groups)
    const int RPB = NCA / RS_V;                     // 32 rows per block

    __shared__ int   ridx[NCA / RS_V];
    __shared__ float rw[NCA / RS_V];
    if (threadIdx.x < RPB) {
        int a = y * RPB + threadIdx.x;
        ridx[threadIdx.x] = ids_a[n * LA + a];
        rw[threadIdx.x]   = g_w_va[n * NCA + a];
    }
    __syncthreads();
    if (g >= LV / 4) return;

    float4 acc = make_float4(0.f, 0.f, 0.f, 0.f);
    const float4* base = (const float4*)cross_av;
    const size_t nhbase = (size_t)nh * LA * (LV / 4);
#pragma unroll 8
    for (int a = 0; a < RPB; a++) {
        float w = rw[a];
        float4 v = __ldg(base + nhbase + (size_t)ridx[a] * (LV / 4) + g);
        acc.x += w * v.x; acc.y += w * v.y; acc.z += w * v.z; acc.w += w * v.w;
    }
    ((float4*)g_vpos)[(size_t)(y * NHNH + nh) * (LV / 4) + g] = acc;
}

// K2: a_pos partial accumulators: acc[c] += w_av[v] * cross_va[n,h,idx_v[v],c]
__global__ void k2_apos(const float* __restrict__ cross_va,
                        const int* __restrict__ ids_v) {
    const int nh = blockIdx.y;
    const int n = nh / HH;
    const int y = blockIdx.x;                 // row split
    const int g = threadIdx.x;                // 128 float4 groups cover LA=512
    const int RPB = NCV / RS_A;               // 49 rows per block

    __shared__ int   ridx[NCV / RS_A];
    __shared__ float rw[NCV / RS_A];
    if (threadIdx.x < RPB) {
        int v = y * RPB + threadIdx.x;
        ridx[threadIdx.x] = ids_v[n * LV + v];
        rw[threadIdx.x]   = g_w_av[n * NCV + v];
    }
    __syncthreads();

    float4 acc = make_float4(0.f, 0.f, 0.f, 0.f);
    const float4* base = (const float4*)cross_va;
    const size_t nhbase = (size_t)nh * LV * (LA / 4);
#pragma unroll 7
    for (int a = 0; a < RPB; a++) {
        float w = rw[a];
        float4 v = __ldg(base + nhbase + (size_t)ridx[a] * (LA / 4) + g);
        acc.x += w * v.x; acc.y += w * v.y; acc.z += w * v.z; acc.w += w * v.w;
    }
    ((float4*)g_apos)[(size_t)(y * NHNH + nh) * (LA / 4) + g] = acc;
}

// K3: pos_v_cls / pos_a_cls: weighted mean over gathered rows of pos_*_q
__global__ void k3_cls(const float* __restrict__ pos_v_q,
                       const float* __restrict__ pos_a_q,
                       const int* __restrict__ ids_v,
                       const int* __restrict__ ids_a,
                       float* __restrict__ out) {
    const int nh = blockIdx.x;
    const int n = nh / HH;
    const int h = nh % HH;
    const int d = threadIdx.x;           // 64 threads = one per headdim
    const bool vside = (blockIdx.y == 0);

    __shared__ int   ridx[NCV];
    __shared__ float rw[NCV];
    const int cnt = vside ? NCV : NCA;
    const int L = vside ? LV : LA;
    const int* ids = vside ? ids_v : ids_a;
    const float* wsrc = vside ? (g_w_av + n * NCV) : (g_w_va + n * NCA);
    const float* q = vside ? pos_v_q : pos_a_q;

    for (int i = threadIdx.x; i < cnt; i += 64) {
        ridx[i] = ids[n * L + i];
        rw[i]   = wsrc[i];
    }
    __syncthreads();

    float acc = 0.f;
    const float* basep = q + (size_t)nh * L * DHD;
#pragma unroll 4
    for (int i = 0; i < cnt; i++)
        acc += basep[(size_t)ridx[i] * DHD + d] * rw[i];

    const float s = vside ? g_sum_av[n] : g_sum_va[n];
    const int off = vside ? 2080 : 2848;
    out[n * OSTR + off + h * DHD + d] = acc / s;
}

// K4: v-side prob: spu dot per head, vpos lookup, sigmoid, head-mean, scatter + prune
__global__ void k4_prob_v(const float* __restrict__ pos_v_k,
                          const float* __restrict__ spu_a_cls,
                          const int* __restrict__ ids_v,
                          const float* __restrict__ u_v,
                          const float* __restrict__ n_attn_av,
                          float* __restrict__ out) {
    const int n = blockIdx.y;
    const int l = blockIdx.x;
    const int h = threadIdx.x >> 5;
    const int lane = threadIdx.x & 31;

    __shared__ int s_row;
    __shared__ float s_sig[HH];
    if (threadIdx.x == 0) s_row = ids_v[n * LV + l];
    __syncthreads();
    const int row = s_row;
    const int nh = n * HH + h;

    const float2* kr = (const float2*)(pos_v_k + ((size_t)nh * LV + row) * DHD);
    const float2* cr = (const float2*)(spu_a_cls + (size_t)nh * DHD);
    float2 a = __ldg(kr + lane);
    float2 b = __ldg(cr + lane);
    float p = a.x * b.x + a.y * b.y;
#pragma unroll
    for (int s = 16; s > 0; s >>= 1) p += __shfl_xor_sync(0xffffffff, p, s);

    if (lane == 0) {
        float spu = p * SCALEF;
        float vp = 0.f;
#pragma unroll
        for (int y = 0; y < RS_V; y++) vp += g_vpos[(size_t)(y * NHNH + nh) * LV + row];
        vp /= g_sum_va[n];
        s_sig[h] = 1.f / (1.f + expf(vp - spu));    // sigmoid(spu - vp)
    }
    __syncthreads();
    if (threadIdx.x == 0) {
        float prob = 0.f;
#pragma unroll
        for (int hh = 0; hh < HH; hh++) prob += s_sig[hh];
        prob *= (1.f / HH);
        float* o = out + n * OSTR;
        o[row] = prob;
        float uu = u_v[n * LV + row];
        o[3616 + row] = (uu < prob) ? 0.f : n_attn_av[n * LV + row];
    }
}

// K5: a-side prob
__global__ void k5_prob_a(const float* __restrict__ pos_a_k,
                          const float* __restrict__ spu_v_cls,
                          const int* __restrict__ ids_a,
                          const float* __restrict__ u_a,
                          const float* __restrict__ n_attn_va,
                          float* __restrict__ out) {
    const int n = blockIdx.y;
    const int l = blockIdx.x;
    const int h = threadIdx.x >> 5;
    const int lane = threadIdx.x & 31;

    __shared__ int s_row;
    __shared__ float s_sig[HH];
    if (threadIdx.x == 0) s_row = ids_a[n * LA + l];
    __syncthreads();
    const int row = s_row;
    const int nh = n * HH + h;

    const float2* kr = (const float2*)(pos_a_k + ((size_t)nh * LA + row) * DHD);
    const float2* cr = (const float2*)(spu_v_cls + (size_t)nh * DHD);
    float2 a = __ldg(kr + lane);
    float2 b = __ldg(cr + lane);
    float p = a.x * b.x + a.y * b.y;
#pragma unroll
    for (int s = 16; s > 0; s >>= 1) p += __shfl_xor_sync(0xffffffff, p, s);

    if (lane == 0) {
        float spu = p * SCALEF;
        float ap = 0.f;
#pragma unroll
        for (int y = 0; y < RS_A; y++) ap += g_apos[(size_t)(y * NHNH + nh) * LA + row];
        ap /= g_sum_av[n];
        s_sig[h] = 1.f / (1.f + expf(ap - spu));
    }
    __syncthreads();
    if (threadIdx.x == 0) {
        float prob = 0.f;
#pragma unroll
        for (int hh = 0; hh < HH; hh++) prob += s_sig[hh];
        prob *= (1.f / HH);
        float* o = out + n * OSTR;
        o[1568 + row] = prob;
        float uu = u_a[n * LA + row];
        o[5184 + row] = (uu < prob) ? 0.f : n_attn_va[n * LA + row];
    }
}

extern "C" void kernel_launch(void* const* d_in, const int* in_sizes, int n_in,
                              void* d_out, int out_size) {
    const float* pos_v_q   = (const float*)d_in[0];
    const float* pos_v_k   = (const float*)d_in[1];
    const float* pos_a_q   = (const float*)d_in[2];
    const float* pos_a_k   = (const float*)d_in[3];
    const float* cross_av  = (const float*)d_in[4];
    const float* cross_va  = (const float*)d_in[5];
    const float* n_attn_av = (const float*)d_in[6];
    const float* n_attn_va = (const float*)d_in[7];
    const float* spu_a_cls = (const float*)d_in[8];
    const float* spu_v_cls = (const float*)d_in[9];
    const float* u_v       = (const float*)d_in[10];
    const float* u_a       = (const float*)d_in[11];
    const int*   ids_v     = (const int*)d_in[12];
    const int*   ids_a     = (const int*)d_in[13];
    float* out = (float*)d_out;

    k0_prep<<<NN, 512>>>(n_attn_av, n_attn_va, ids_v, ids_a, out);
    k1_vpos<<<dim3(2, RS_V, NHNH), 256>>>(cross_av, ids_a);
    k2_apos<<<dim3(RS_A, NHNH), 128>>>(cross_va, ids_v);
    k3_cls<<<dim3(NHNH, 2), 64>>>(pos_v_q, pos_a_q, ids_v, ids_a, out);
    k4_prob_v<<<dim3(NCV, NN), 384>>>(pos_v_k, spu_a_cls, ids_v, u_v, n_attn_av, out);
    k5_prob_a<<<dim3(NCA, NN), 384>>>(pos_a_k, spu_v_cls, ids_a, u_a, n_attn_va, out);
}

// round 4
// speedup vs baseline: 1.5688x; 1.5688x over previous
#include <cuda_runtime.h>
#include <math.h>

#define NN 8
#define HH 12
#define DHD 64
#define LV 1568
#define LA 512
#define NCV 392
#define NCA 256
#define NHNH (NN*HH)          // 96
#define OSTR 5696             // output row stride
#define RS_V 8                // row-splits for v_pos accumulation (256/8 = 32 rows per block)
#define RS_A 8                // row-splits for a_pos accumulation (392/8 = 49 rows per block)
#define SCALEF 0.125f

// ---- scratch (device globals; no allocation allowed) ----
__device__ float g_w_av[NN * NCV];
__device__ float g_w_va[NN * NCA];
__device__ float g_sum_av[NN];
__device__ float g_sum_va[NN];
__device__ float g_vpos[RS_V * NHNH * LV];   // partial accumulators, full LV columns
__device__ float g_apos[RS_A * NHNH * LA];   // partial accumulators, full LA columns

// K0: gather weights, compute their sums, fill output defaults (prob=0, prune=n_attn)
__global__ void k0_prep(const float* __restrict__ n_attn_av,
                        const float* __restrict__ n_attn_va,
                        const int* __restrict__ ids_v,
                        const int* __restrict__ ids_a,
                        float* __restrict__ out) {
    int n = blockIdx.x;
    int t = threadIdx.x;             // 512 threads
    __shared__ float red[512];

    float wv = 0.f;
    if (t < NCV) {
        int p = ids_v[n * LV + t];
        wv = n_attn_av[n * LV + p];
        g_w_av[n * NCV + t] = wv;
    }
    red[t] = wv;
    __syncthreads();
    for (int s = 256; s > 0; s >>= 1) {
        if (t < s) red[t] += red[t + s];
        __syncthreads();
    }
    if (t == 0) g_sum_av[n] = red[0];
    __syncthreads();

    float wa = 0.f;
    if (t < NCA) {
        int p = ids_a[n * LA + t];
        wa = n_attn_va[n * LA + p];
        g_w_va[n * NCA + t] = wa;
    }
    red[t] = wa;
    __syncthreads();
    for (int s = 256; s > 0; s >>= 1) {
        if (t < s) red[t] += red[t + s];
        __syncthreads();
    }
    if (t == 0) g_sum_va[n] = red[0];

    // output defaults
    float* o = out + n * OSTR;
    for (int i = t; i < LV + LA; i += 512) o[i] = 0.f;                       // prob regions
    for (int i = t; i < LV; i += 512) o[3616 + i] = n_attn_av[n * LV + i];   // prune_av default
    for (int i = t; i < LA; i += 512) o[5184 + i] = n_attn_va[n * LA + i];   // prune_va default
}

// K1: v_pos partial accumulators: acc[c] += w_va[a] * cross_av[n,h,idx_a[a],c] over a row-split
__global__ void k1_vpos(const float* __restrict__ cross_av,
                        const int* __restrict__ ids_a) {
    const int nh = blockIdx.z;
    const int n = nh / HH;
    const int y = blockIdx.y;                       // row split
    const int g = blockIdx.x * 256 + threadIdx.x;   // float4 column group (LV/4 = 392 groups)
    const int RPB = NCA / RS_V;                     // 32 rows per block

    __shared__ int   ridx[NCA / RS_V];
    __shared__ float rw[NCA / RS_V];
    if (threadIdx.x < RPB) {
        int a = y * RPB + threadIdx.x;
        ridx[threadIdx.x] = ids_a[n * LA + a];
        rw[threadIdx.x]   = g_w_va[n * NCA + a];
    }
    __syncthreads();
    if (g >= LV / 4) return;

    float4 acc = make_float4(0.f, 0.f, 0.f, 0.f);
    const float4* base = (const float4*)cross_av;
    const size_t nhbase = (size_t)nh * LA * (LV / 4);
#pragma unroll 8
    for (int a = 0; a < RPB; a++) {
        float w = rw[a];
        float4 v = __ldg(base + nhbase + (size_t)ridx[a] * (LV / 4) + g);
        acc.x += w * v.x; acc.y += w * v.y; acc.z += w * v.z; acc.w += w * v.w;
    }
    ((float4*)g_vpos)[(size_t)(y * NHNH + nh) * (LV / 4) + g] = acc;
}

// K2: a_pos partial accumulators: acc[c] += w_av[v] * cross_va[n,h,idx_v[v],c]
__global__ void k2_apos(const float* __restrict__ cross_va,
                        const int* __restrict__ ids_v) {
    const int nh = blockIdx.y;
    const int n = nh / HH;
    const int y = blockIdx.x;                 // row split
    const int g = threadIdx.x;                // 128 float4 groups cover LA=512
    const int RPB = NCV / RS_A;               // 49 rows per block

    __shared__ int   ridx[NCV / RS_A];
    __shared__ float rw[NCV / RS_A];
    if (threadIdx.x < RPB) {
        int v = y * RPB + threadIdx.x;
        ridx[threadIdx.x] = ids_v[n * LV + v];
        rw[threadIdx.x]   = g_w_av[n * NCV + v];
    }
    __syncthreads();

    float4 acc = make_float4(0.f, 0.f, 0.f, 0.f);
    const float4* base = (const float4*)cross_va;
    const size_t nhbase = (size_t)nh * LV * (LA / 4);
#pragma unroll 7
    for (int a = 0; a < RPB; a++) {
        float w = rw[a];
        float4 v = __ldg(base + nhbase + (size_t)ridx[a] * (LA / 4) + g);
        acc.x += w * v.x; acc.y += w * v.y; acc.z += w * v.z; acc.w += w * v.w;
    }
    ((float4*)g_apos)[(size_t)(y * NHNH + nh) * (LA / 4) + g] = acc;
}

// K3: pos_v_cls / pos_a_cls: weighted mean over gathered rows of pos_*_q
// 512 threads = 8 sub-groups x 64 lanes; sub-group s handles rows s, s+8, ...
// then shared reduce over the 8 partials. 8x the warps + 8x MLP vs old version.
__global__ void k3_cls(const float* __restrict__ pos_v_q,
                       const float* __restrict__ pos_a_q,
                       const int* __restrict__ ids_v,
                       const int* __restrict__ ids_a,
                       float* __restrict__ out) {
    const int nh = blockIdx.x;
    const int n = nh / HH;
    const int h = nh % HH;
    const int d = threadIdx.x & 63;      // headdim lane
    const int sub = threadIdx.x >> 6;    // 0..7
    const bool vside = (blockIdx.y == 0);

    __shared__ int   ridx[NCV];
    __shared__ float rw[NCV];
    __shared__ float part[8 * DHD];

    const int cnt = vside ? NCV : NCA;
    const int L = vside ? LV : LA;
    const int* ids = vside ? ids_v : ids_a;
    const float* wsrc = vside ? (g_w_av + n * NCV) : (g_w_va + n * NCA);
    const float* q = vside ? pos_v_q : pos_a_q;

    for (int i = threadIdx.x; i < cnt; i += 512) {
        ridx[i] = ids[n * L + i];
        rw[i]   = wsrc[i];
    }
    __syncthreads();

    float acc = 0.f;
    const float* basep = q + (size_t)nh * L * DHD;
#pragma unroll 7
    for (int i = sub; i < cnt; i += 8)
        acc += __ldg(basep + (size_t)ridx[i] * DHD + d) * rw[i];

    part[sub * DHD + d] = acc;
    __syncthreads();

    if (sub == 0) {
        float tot = acc;
#pragma unroll
        for (int s = 1; s < 8; s++) tot += part[s * DHD + d];
        const float su = vside ? g_sum_av[n] : g_sum_va[n];
        const int off = vside ? 2080 : 2848;
        out[n * OSTR + off + h * DHD + d] = tot / su;
    }
}

// K4: v-side prob: spu dot per head, vpos lookup, sigmoid, head-mean, scatter + prune
__global__ void k4_prob_v(const float* __restrict__ pos_v_k,
                          const float* __restrict__ spu_a_cls,
                          const int* __restrict__ ids_v,
                          const float* __restrict__ u_v,
                          const float* __restrict__ n_attn_av,
                          float* __restrict__ out) {
    const int n = blockIdx.y;
    const int l = blockIdx.x;
    const int h = threadIdx.x >> 5;
    const int lane = threadIdx.x & 31;

    __shared__ int s_row;
    __shared__ float s_sig[HH];
    if (threadIdx.x == 0) s_row = ids_v[n * LV + l];
    __syncthreads();
    const int row = s_row;
    const int nh = n * HH + h;

    const float2* kr = (const float2*)(pos_v_k + ((size_t)nh * LV + row) * DHD);
    const float2* cr = (const float2*)(spu_a_cls + (size_t)nh * DHD);
    float2 a = __ldg(kr + lane);
    float2 b = __ldg(cr + lane);
    float p = a.x * b.x + a.y * b.y;
#pragma unroll
    for (int s = 16; s > 0; s >>= 1) p += __shfl_xor_sync(0xffffffff, p, s);

    if (lane == 0) {
        float spu = p * SCALEF;
        float vp = 0.f;
#pragma unroll
        for (int y = 0; y < RS_V; y++) vp += g_vpos[(size_t)(y * NHNH + nh) * LV + row];
        vp /= g_sum_va[n];
        s_sig[h] = 1.f / (1.f + expf(vp - spu));    // sigmoid(spu - vp)
    }
    __syncthreads();
    if (threadIdx.x == 0) {
        float prob = 0.f;
#pragma unroll
        for (int hh = 0; hh < HH; hh++) prob += s_sig[hh];
        prob *= (1.f / HH);
        float* o = out + n * OSTR;
        o[row] = prob;
        float uu = u_v[n * LV + row];
        o[3616 + row] = (uu < prob) ? 0.f : n_attn_av[n * LV + row];
    }
}

// K5: a-side prob
__global__ void k5_prob_a(const float* __restrict__ pos_a_k,
                          const float* __restrict__ spu_v_cls,
                          const int* __restrict__ ids_a,
                          const float* __restrict__ u_a,
                          const float* __restrict__ n_attn_va,
                          float* __restrict__ out) {
    const int n = blockIdx.y;
    const int l = blockIdx.x;
    const int h = threadIdx.x >> 5;
    const int lane = threadIdx.x & 31;

    __shared__ int s_row;
    __shared__ float s_sig[HH];
    if (threadIdx.x == 0) s_row = ids_a[n * LA + l];
    __syncthreads();
    const int row = s_row;
    const int nh = n * HH + h;

    const float2* kr = (const float2*)(pos_a_k + ((size_t)nh * LA + row) * DHD);
    const float2* cr = (const float2*)(spu_v_cls + (size_t)nh * DHD);
    float2 a = __ldg(kr + lane);
    float2 b = __ldg(cr + lane);
    float p = a.x * b.x + a.y * b.y;
#pragma unroll
    for (int s = 16; s > 0; s >>= 1) p += __shfl_xor_sync(0xffffffff, p, s);

    if (lane == 0) {
        float spu = p * SCALEF;
        float ap = 0.f;
#pragma unroll
        for (int y = 0; y < RS_A; y++) ap += g_apos[(size_t)(y * NHNH + nh) * LA + row];
        ap /= g_sum_av[n];
        s_sig[h] = 1.f / (1.f + expf(ap - spu));
    }
    __syncthreads();
    if (threadIdx.x == 0) {
        float prob = 0.f;
#pragma unroll
        for (int hh = 0; hh < HH; hh++) prob += s_sig[hh];
        prob *= (1.f / HH);
        float* o = out + n * OSTR;
        o[1568 + row] = prob;
        float uu = u_a[n * LA + row];
        o[5184 + row] = (uu < prob) ? 0.f : n_attn_va[n * LA + row];
    }
}

extern "C" void kernel_launch(void* const* d_in, const int* in_sizes, int n_in,
                              void* d_out, int out_size) {
    const float* pos_v_q   = (const float*)d_in[0];
    const float* pos_v_k   = (const float*)d_in[1];
    const float* pos_a_q   = (const float*)d_in[2];
    const float* pos_a_k   = (const float*)d_in[3];
    const float* cross_av  = (const float*)d_in[4];
    const float* cross_va  = (const float*)d_in[5];
    const float* n_attn_av = (const float*)d_in[6];
    const float* n_attn_va = (const float*)d_in[7];
    const float* spu_a_cls = (const float*)d_in[8];
    const float* spu_v_cls = (const float*)d_in[9];
    const float* u_v       = (const float*)d_in[10];
    const float* u_a       = (const float*)d_in[11];
    const int*   ids_v     = (const int*)d_in[12];
    const int*   ids_a     = (const int*)d_in[13];
    float* out = (float*)d_out;

    k0_prep<<<NN, 512>>>(n_attn_av, n_attn_va, ids_v, ids_a, out);
    k1_vpos<<<dim3(2, RS_V, NHNH), 256>>>(cross_av, ids_a);
    k2_apos<<<dim3(RS_A, NHNH), 128>>>(cross_va, ids_v);
    k3_cls<<<dim3(NHNH, 2), 512>>>(pos_v_q, pos_a_q, ids_v, ids_a, out);
    k4_prob_v<<<dim3(NCV, NN), 384>>>(pos_v_k, spu_a_cls, ids_v, u_v, n_attn_av, out);
    k5_prob_a<<<dim3(NCA, NN), 384>>>(pos_a_k, spu_v_cls, ids_a, u_a, n_attn_va, out);
}